// round 10
// baseline (speedup 1.0000x reference)
#include <cuda_runtime.h>
#include <cuda_fp16.h>
#include <mma.h>
#include <cstdint>

using namespace nvcuda;

// Problem constants (shapes fixed by the reference)
#define NNODES 15360       // 512 graphs * 30 nodes
#define HID 64
#define NPG 30             // nodes per graph
#define NBR 41             // branches per graph
#define NEPG 82            // edges per graph (bidirectional)
#define NLAYERS 5
#define QCOLS 2112         // 32*64 (w-part) + 64 (b2-part)
#define QPAD 2120          // padded Q smem row stride (halfs)
#define NT 132             // QCOLS / 16 n-tiles
#define FTHREADS 512
#define BN_EPS 1e-5f

// k_fused dynamic smem layout (bytes)
#define F_SH    0                    // float[1920]   h tile
#define F_SH16  7680                 // half[32*72]   fp16 A operand
#define F_SAGG  12288                // float[1920]   agg
#define F_SZ    19968                // float[96*32]  z
#define F_EA    32256                // half[96*136] ea | float stage[16*320] | float Wr[4096]
#define F_W1H   58368                // half[128*40]  W1 fp16
#define F_SDEG  68608                // float[30]
#define F_SSE   68736                // int[82]
#define F_SDE   69064                // int[82]
#define F_Q     69408                // half[30*2120] Q tile
#define F_TOT   (69408 + 30 * QPAD * 2)   // 196608 bytes

// ---------------- scratch (device globals; no allocation allowed) -----------
__device__ float g_h0[NNODES * HID];
__device__ float g_h1[NNODES * HID];
__device__ __half g_Ws[(size_t)NLAYERS * QCOLS * HID];      // W2p^T [l][n][64] fp16

// ---------------- prep kernels ----------------------------------------------
__global__ void k_wsplit(const float* __restrict__ W2, const float* __restrict__ b2,
                         __half* __restrict__ Ws) {
    int idx = blockIdx.x * blockDim.x + threadIdx.x;
    const int total = NLAYERS * QCOLS * HID;
    if (idx >= total) return;
    int k = idx & 63;
    int n = (idx >> 6) % QCOLS;
    int l = idx / (QCOLS * HID);
    float v;
    if (n < 2048) {
        int j = n >> 6, o = n & 63;
        v = W2[(size_t)(l * 32 + j) * 4096 + k * 64 + o];
    } else {
        v = b2[(size_t)l * 4096 + k * 64 + (n - 2048)];
    }
    Ws[idx] = __float2half_rn(v);
}

// h0 = x @ Wp + bp
__global__ void k_proj(const float* __restrict__ x, const float* __restrict__ Wp,
                       const float* __restrict__ bp, float* __restrict__ h, int N) {
    int t = blockIdx.x * blockDim.x + threadIdx.x;
    if (t >= N * HID) return;
    int n = t >> 6, c = t & 63;
    const float* xr = x + n * 8;
    float acc = bp[c];
#pragma unroll
    for (int k = 0; k < 8; k++) acc += xr[k] * Wp[k * 64 + c];
    h[t] = acc;
}

// ---------------- mega-fused per-graph layer kernel --------------------------
// per block (graph): z (WMMA) -> Q tile in smem (WMMA vs L2-resident W) ->
// msg gather from smem Q -> scatter-mean -> root GEMM + BN + relu + residual
__global__ __launch_bounds__(FTHREADS) void k_fused(
    const float* __restrict__ h, const int* __restrict__ src, const int* __restrict__ dst,
    const __half* __restrict__ Wl, const float* __restrict__ W1l, const float* __restrict__ b1l,
    const float* __restrict__ Wr, const float* __restrict__ br,
    const float* __restrict__ gamma, const float* __restrict__ beta,
    const float* __restrict__ rmean, const float* __restrict__ rvar,
    float* __restrict__ hout, int E2) {
    extern __shared__ char smraw[];
    float* sh    = (float*)(smraw + F_SH);
    __half* sh16 = (__half*)(smraw + F_SH16);
    float* sagg  = (float*)(smraw + F_SAGG);
    float* sz    = (float*)(smraw + F_SZ);
    __half* ea   = (__half*)(smraw + F_EA);
    float* stage = (float*)(smraw + F_EA);   // aliased scratch
    float* sWr   = (float*)(smraw + F_EA);   // aliased scratch
    __half* w1h  = (__half*)(smraw + F_W1H);
    float* sdeg  = (float*)(smraw + F_SDEG);
    int* sse     = (int*)(smraw + F_SSE);
    int* sde     = (int*)(smraw + F_SDE);
    __half* Qsm  = (__half*)(smraw + F_Q);

    const int g = blockIdx.x;
    const int tid = threadIdx.x;
    const int w = tid >> 5;
    const int lane = tid & 31;
    const int nbase = g * NPG;

    // phase A: load h tile, zero agg, fp16 A operand (padded 32x72), W1->fp16
    for (int i = tid; i < NPG * HID; i += FTHREADS) {
        sh[i] = h[nbase * HID + i];
        sagg[i] = 0.f;
    }
    for (int i = tid; i < 32 * 72; i += FTHREADS) {
        int r = i / 72, c = i - r * 72;
        __half v = __float2half_rn(0.f);
        if (r < NPG && c < 64) v = __float2half_rn(h[nbase * HID + r * 64 + c]);
        sh16[i] = v;
    }
    for (int i = tid; i < 128 * 32; i += FTHREADS)
        w1h[(i >> 5) * 40 + (i & 31)] = __float2half_rn(W1l[i]);
    if (tid < NPG) sdeg[tid] = 0.f;
    __syncthreads();

    // phase B: edge indices + degree
    if (tid < NEPG) {
        int k = tid;
        int ei = (k < NBR) ? g * NBR + k : E2 + g * NBR + (k - NBR);
        int s = src[ei] - nbase;
        int d = dst[ei] - nbase;
        sse[k] = s; sde[k] = d;
        atomicAdd(&sdeg[d], 1.0f);
    }
    __syncthreads();

    // phase C: build ea[96][136] fp16 = [h[src] | h[dst]] per edge row
    for (int i = tid; i < 96 * 128; i += FTHREADS) {
        int k = i >> 7, c = i & 127;
        float v = 0.f;
        if (k < NEPG) {
            int node = (c < 64) ? sse[k] : sde[k];
            v = sh[node * 64 + (c & 63)];
        }
        ea[k * 136 + c] = __float2half_rn(v);
    }
    __syncthreads();

    // phase D: z = ea @ W1 via WMMA; 12 warp-tiles (6m x 2n)
    if (w < 12) {
        int mt = w >> 1, nt = w & 1;
        wmma::fragment<wmma::accumulator, 16, 16, 16, float> acc;
        wmma::fill_fragment(acc, 0.f);
#pragma unroll
        for (int kk = 0; kk < 8; kk++) {
            wmma::fragment<wmma::matrix_a, 16, 16, 16, __half, wmma::row_major> af;
            wmma::fragment<wmma::matrix_b, 16, 16, 16, __half, wmma::row_major> bf;
            wmma::load_matrix_sync(af, ea + (mt * 16) * 136 + kk * 16, 136);
            wmma::load_matrix_sync(bf, w1h + (kk * 16) * 40 + nt * 16, 40);
            wmma::mma_sync(acc, af, bf, acc);
        }
        wmma::store_matrix_sync(sz + mt * 16 * 32 + nt * 16, acc, 32, wmma::mem_row_major);
    }
    __syncthreads();

    // phase E: bias + relu on z
    for (int i = tid; i < NEPG * 32; i += FTHREADS)
        sz[i] = fmaxf(sz[i] + b1l[i & 31], 0.f);
    __syncthreads();

    // phase Q: Q tile = sh16[32x64] @ W^T -> Qsm[30][2112], WMMA.
    // A fragments register-resident; B fragments straight from L2-resident W.
    {
        float* wstage = stage + w * 320;  // 16x20 fp32 per warp
        wmma::fragment<wmma::matrix_a, 16, 16, 16, __half, wmma::row_major> af[2][4];
#pragma unroll
        for (int i = 0; i < 2; i++)
#pragma unroll
            for (int kk = 0; kk < 4; kk++)
                wmma::load_matrix_sync(af[i][kk], sh16 + (i * 16) * 72 + kk * 16, 72);

        for (int nt = w; nt < NT; nt += 16) {
            const __half* Wb = Wl + (size_t)nt * 16 * 64;
            wmma::fragment<wmma::matrix_b, 16, 16, 16, __half, wmma::col_major> bf[4];
#pragma unroll
            for (int kk = 0; kk < 4; kk++)
                wmma::load_matrix_sync(bf[kk], Wb + kk * 16, 64);
            wmma::fragment<wmma::accumulator, 16, 16, 16, float> acc[2];
#pragma unroll
            for (int i = 0; i < 2; i++) wmma::fill_fragment(acc[i], 0.f);
#pragma unroll
            for (int kk = 0; kk < 4; kk++)
#pragma unroll
                for (int i = 0; i < 2; i++)
                    wmma::mma_sync(acc[i], af[i][kk], bf[kk], acc[i]);
            // convert + store to smem Q (rows < 30 only)
#pragma unroll
            for (int i = 0; i < 2; i++) {
                wmma::store_matrix_sync(wstage, acc[i], 20, wmma::mem_row_major);
                __syncwarp();
                int r = (lane >> 1) + i * 16;
                int c0 = (lane & 1) * 8;
                if (r < NPG) {
                    const float* sr = wstage + (lane >> 1) * 20 + c0;
                    half2 hv[4];
#pragma unroll
                    for (int q = 0; q < 4; q++)
                        hv[q] = __floats2half2_rn(sr[2 * q], sr[2 * q + 1]);
                    *(uint4*)(Qsm + r * QPAD + nt * 16 + c0) = *(uint4*)hv;
                }
                __syncwarp();
            }
        }
    }
    __syncthreads();

    // phase F: msg gather (warp per edge) from smem Q, smem scatter
    const int c = lane & 7;    // o-chunk: outputs c*8 .. c*8+7
    const int jo = lane >> 3;  // j offset within group of 4
    for (int k = w; k < NEPG; k += FTHREADS / 32) {
        int s = sse[k], d = sde[k];
        const __half* Qs = Qsm + s * QPAD;
        float zval = sz[k * 32 + lane];
        float acc[8];
#pragma unroll
        for (int i = 0; i < 8; i++) acc[i] = 0.f;
#pragma unroll
        for (int j0 = 0; j0 < 8; j0++) {
            int j = j0 * 4 + jo;
            float zz = __shfl_sync(0xffffffffu, zval, j);
            uint4 qv = *(const uint4*)(Qs + j * 64 + c * 8);
            const half2* qh = (const half2*)&qv;
#pragma unroll
            for (int i = 0; i < 4; i++) {
                float2 f = __half22float2(qh[i]);
                acc[2 * i] += zz * f.x;
                acc[2 * i + 1] += zz * f.y;
            }
        }
#pragma unroll
        for (int i = 0; i < 8; i++) {
            acc[i] += __shfl_xor_sync(0xffffffffu, acc[i], 8);
            acc[i] += __shfl_xor_sync(0xffffffffu, acc[i], 16);
        }
        int o = c * 8 + jo * 2;
        float2 bias = __half22float2(*(const half2*)(Qs + 2048 + o));
        atomicAdd(&sagg[d * 64 + o], acc[jo * 2] + bias.x);
        atomicAdd(&sagg[d * 64 + o + 1], acc[jo * 2 + 1] + bias.y);
    }
    __syncthreads();

    // phase G: load Wr (fp32) into aliased scratch
    for (int i = tid; i < 64 * 64; i += FTHREADS) sWr[i] = Wr[i];
    __syncthreads();

    // phase H: node update
    for (int i = tid; i < NPG * HID; i += FTHREADS) {
        int n = i >> 6, cc = i & 63;
        const float* hr = sh + n * 64;
        float acc = br[cc];
#pragma unroll
        for (int kk = 0; kk < 64; kk++) acc += hr[kk] * sWr[kk * 64 + cc];
        float h2 = sagg[i] / fmaxf(sdeg[n], 1.0f) + acc;
        float scale = gamma[cc] * rsqrtf(rvar[cc] + BN_EPS);
        h2 = (h2 - rmean[cc]) * scale + beta[cc];
        float r = fmaxf(h2, 0.f) + sh[i];
        hout[nbase * HID + i] = r;
    }
}

// out[i] = relu([h[u]|h[v]] @ Wm1 + bm1) @ Wm2 + bm2 ; one warp per output row
__global__ void k_final(const float* __restrict__ h, const int* __restrict__ bu,
                        const int* __restrict__ bv, const float* __restrict__ Wm1,
                        const float* __restrict__ bm1, const float* __restrict__ Wm2,
                        const float* __restrict__ bm2, float* __restrict__ out,
                        int nout, int B, int npg) {
    int i = (blockIdx.x * blockDim.x + threadIdx.x) >> 5;
    int lane = threadIdx.x & 31;
    if (i >= nout) return;
    int g = i / B, b = i - g * B;
    int u = bu[b] + g * npg;
    int v = bv[b] + g * npg;
    const float* hu = h + (size_t)u * 64;
    const float* hv = h + (size_t)v * 64;
    float a0 = bm1[lane], a1 = bm1[lane + 32];
#pragma unroll
    for (int k = 0; k < 64; k++) {
        float x0 = hu[k];
        a0 += x0 * Wm1[k * 64 + lane];
        a1 += x0 * Wm1[k * 64 + lane + 32];
    }
#pragma unroll
    for (int k = 0; k < 64; k++) {
        float x1 = hv[k];
        a0 += x1 * Wm1[(64 + k) * 64 + lane];
        a1 += x1 * Wm1[(64 + k) * 64 + lane + 32];
    }
    float r = fmaxf(a0, 0.f) * Wm2[lane] + fmaxf(a1, 0.f) * Wm2[lane + 32];
#pragma unroll
    for (int off = 16; off; off >>= 1) r += __shfl_down_sync(0xffffffffu, r, off);
    if (lane == 0) out[i] = r + bm2[0];
}

extern "C" void kernel_launch(void* const* d_in, const int* in_sizes, int n_in,
                              void* d_out, int out_size) {
    const float* x   = (const float*)d_in[0];
    const int* eidx  = (const int*)d_in[1];
    const int* bu    = (const int*)d_in[2];
    const int* bv    = (const int*)d_in[3];
    int base = (in_sizes[4] == 1) ? 5 : 4;
    const float* Wp    = (const float*)d_in[base + 0];
    const float* bp    = (const float*)d_in[base + 1];
    const float* W1    = (const float*)d_in[base + 2];
    const float* b1    = (const float*)d_in[base + 3];
    const float* W2    = (const float*)d_in[base + 4];
    const float* b2    = (const float*)d_in[base + 5];
    const float* Wr    = (const float*)d_in[base + 6];
    const float* br    = (const float*)d_in[base + 7];
    const float* gamma = (const float*)d_in[base + 8];
    const float* beta  = (const float*)d_in[base + 9];
    const float* rmean = (const float*)d_in[base + 10];
    const float* rvar  = (const float*)d_in[base + 11];
    const float* Wm1   = (const float*)d_in[base + 12];
    const float* bm1   = (const float*)d_in[base + 13];
    const float* Wm2   = (const float*)d_in[base + 14];
    const float* bm2   = (const float*)d_in[base + 15];

    const int Nn = in_sizes[0] / 8;     // 15360
    const int E  = in_sizes[1] / 2;     // 41984
    const int B  = in_sizes[2];         // 41
    const int G  = out_size / B;        // 512
    const int npg = Nn / G;             // 30
    const int* src = eidx;
    const int* dst = eidx + E;
    const int E2 = E / 2;

    static float *p_h0 = nullptr, *p_h1;
    static __half* p_Ws;
    if (!p_h0) {
        cudaGetSymbolAddress((void**)&p_h0, g_h0);
        cudaGetSymbolAddress((void**)&p_h1, g_h1);
        cudaGetSymbolAddress((void**)&p_Ws, g_Ws);
        cudaFuncSetAttribute(k_fused, cudaFuncAttributeMaxDynamicSharedMemorySize, F_TOT);
    }

    // launches: 0=proj, 1=wsplit, 2..6=fused(l0..l4), 7=final
    // ncu -s 5 -> fused layer 3
    const int WTOT = NLAYERS * QCOLS * HID;
    k_proj<<<(Nn * HID + 255) / 256, 256>>>(x, Wp, bp, p_h0, Nn);
    k_wsplit<<<(WTOT + 255) / 256, 256>>>(W2, b2, p_Ws);

    float* cur = p_h0;
    float* nxt = p_h1;
    for (int l = 0; l < NLAYERS; l++) {
        k_fused<<<G, FTHREADS, F_TOT>>>(cur, src, dst,
                            p_Ws + (size_t)l * QCOLS * HID,
                            W1 + (size_t)l * 128 * 32, b1 + (size_t)l * 32,
                            Wr + (size_t)l * 64 * 64, br + (size_t)l * 64,
                            gamma + (size_t)l * 64, beta + (size_t)l * 64,
                            rmean + (size_t)l * 64, rvar + (size_t)l * 64,
                            nxt, E2);
        float* tmp = cur; cur = nxt; nxt = tmp;
    }
    k_final<<<(out_size + 7) / 8, 256>>>(cur, bu, bv, Wm1, bm1, Wm2, bm2,
                                         (float*)d_out, out_size, B, npg);
}

// round 11
// speedup vs baseline: 1.3040x; 1.3040x over previous
#include <cuda_runtime.h>
#include <cuda_fp16.h>
#include <mma.h>
#include <cstdint>

using namespace nvcuda;

// Problem constants (shapes fixed by the reference)
#define NNODES 15360       // 512 graphs * 30 nodes
#define HID 64
#define NPG 30             // nodes per graph
#define NBR 41             // branches per graph
#define NEPG 82            // edges per graph (bidirectional)
#define NLAYERS 5
#define QCOLS 2112         // 32*64 (w-part) + 64 (b2-part)
#define APAD 72            // padded smem stride for A (halfs)
#define BPAD 72            // padded smem stride for B (halfs)
#define FTHREADS 512       // k_fused block size
#define BN_EPS 1e-5f

// k_fused dynamic smem layout (bytes)
#define F_SH    0                    // float[1920]  h tile
#define F_SAGG  7680                 // float[1920]  agg
#define F_SZ    15360                // float[96*32] z
#define F_EA    27648                // half[96*136] ea  (reused: float Wr[4096])
#define F_W1H   53760                // half[128*40] W1 fp16
#define F_SDEG  64000                // float[30]
#define F_SSE   64120                // int[82]
#define F_SDE   64448                // int[82]
#define F_TOT   64776

// ---------------- scratch (device globals; no allocation allowed) -----------
__device__ float g_h0[NNODES * HID];
__device__ float g_h1[NNODES * HID];
__device__ __half g_Q[(size_t)NNODES * QCOLS];              // ~65 MB fp16
__device__ __half g_hs[(size_t)NNODES * HID];               // fp16 h
__device__ __half g_Ws[(size_t)NLAYERS * QCOLS * HID];      // B  [l][n][64] fp16

// ---------------- prep kernels ----------------------------------------------
// Ws[l][n][k] = fp16(W2p[k][n]); cols 0..2047 from W2, 2048..2111 from b2
__global__ void k_wsplit(const float* __restrict__ W2, const float* __restrict__ b2,
                         __half* __restrict__ Ws, int lo0, int hi0) {
    int idx = lo0 + blockIdx.x * blockDim.x + threadIdx.x;
    if (idx >= hi0) return;
    int k = idx & 63;
    int n = (idx >> 6) % QCOLS;
    int l = idx / (QCOLS * HID);
    float v;
    if (n < 2048) {
        int j = n >> 6, o = n & 63;
        v = W2[(size_t)(l * 32 + j) * 4096 + k * 64 + o];
    } else {
        v = b2[(size_t)l * 4096 + k * 64 + (n - 2048)];
    }
    Ws[idx] = __float2half_rn(v);
}

// h0 = x @ Wp + bp  (+ fp16 copy of h0)
__global__ void k_proj(const float* __restrict__ x, const float* __restrict__ Wp,
                       const float* __restrict__ bp, float* __restrict__ h,
                       __half* __restrict__ hs, int N) {
    int t = blockIdx.x * blockDim.x + threadIdx.x;
    if (t >= N * HID) return;
    int n = t >> 6, c = t & 63;
    const float* xr = x + n * 8;
    float acc = bp[c];
#pragma unroll
    for (int k = 0; k < 8; k++) acc += xr[k] * Wp[k * 64 + c];
    h[t] = acc;
    hs[t] = __float2half_rn(acc);
}

// ---------------- WMMA fp16 GEMM: Q = h(15360x64) @ W^T(64x2112) -------------
// block: 128 M x (2 x 96) N subtiles; fp16 accum, direct global store.
__global__ __launch_bounds__(256, 3) void k_qwmma(const __half* __restrict__ A,
                                                  const __half* __restrict__ B,
                                                  __half* __restrict__ Q) {
    extern __shared__ __half sm[];
    __half* As = sm;                          // 128 x APAD
    __half* Bs = sm + 128 * APAD;             // 2 x (96 x BPAD)
    const int m0 = blockIdx.y * 128;
    const int n0 = blockIdx.x * 192;
    const int t = threadIdx.x;

    for (int i = t; i < 128 * 8; i += 256) {
        int r = i >> 3, c = (i & 7) * 8;
        *(uint4*)(As + r * APAD + c) = *(const uint4*)(A + (size_t)(m0 + r) * HID + c);
    }
    for (int i = t; i < 2 * 96 * 8; i += 256) {
        int s = i / 768;
        int r = (i % 768) >> 3, c = (i & 7) * 8;
        *(uint4*)(Bs + s * 96 * BPAD + r * BPAD + c) =
            *(const uint4*)(B + (size_t)(n0 + s * 96 + r) * HID + c);
    }
    __syncthreads();

    const int w = t >> 5;
    const int mw = (w & 3) * 32;
    const int nw = (w >> 2) * 48;

#pragma unroll
    for (int s = 0; s < 2; s++) {
        const __half* Bsub = Bs + s * 96 * BPAD;
        wmma::fragment<wmma::accumulator, 16, 16, 16, __half> acc[2][3];
#pragma unroll
        for (int i = 0; i < 2; i++)
#pragma unroll
            for (int j = 0; j < 3; j++) wmma::fill_fragment(acc[i][j], __float2half(0.f));

#pragma unroll
        for (int kk = 0; kk < 4; kk++) {
            wmma::fragment<wmma::matrix_b, 16, 16, 16, __half, wmma::col_major> bf[3];
#pragma unroll
            for (int j = 0; j < 3; j++)
                wmma::load_matrix_sync(bf[j], Bsub + (nw + j * 16) * BPAD + kk * 16, BPAD);
            wmma::fragment<wmma::matrix_a, 16, 16, 16, __half, wmma::row_major> af[2];
#pragma unroll
            for (int i = 0; i < 2; i++)
                wmma::load_matrix_sync(af[i], As + (mw + i * 16) * APAD + kk * 16, APAD);
#pragma unroll
            for (int i = 0; i < 2; i++)
#pragma unroll
                for (int j = 0; j < 3; j++)
                    wmma::mma_sync(acc[i][j], af[i], bf[j], acc[i][j]);
        }

        // epilogue: store fp16 accumulators straight to global
#pragma unroll
        for (int i = 0; i < 2; i++)
#pragma unroll
            for (int j = 0; j < 3; j++)
                wmma::store_matrix_sync(
                    Q + (size_t)(m0 + mw + i * 16) * QCOLS + n0 + s * 96 + nw + j * 16,
                    acc[i][j], QCOLS, wmma::mem_row_major);
    }
}

// ---------------- fused per-graph layer kernel --------------------------------
// z via WMMA (ea[96,128] @ W1[128,32]), then msg gather, smem scatter, node update
__global__ __launch_bounds__(FTHREADS, 2) void k_fused(
    const float* __restrict__ h, const int* __restrict__ src, const int* __restrict__ dst,
    const __half* __restrict__ Qh, const float* __restrict__ W1l, const float* __restrict__ b1l,
    const float* __restrict__ Wr, const float* __restrict__ br,
    const float* __restrict__ gamma, const float* __restrict__ beta,
    const float* __restrict__ rmean, const float* __restrict__ rvar,
    float* __restrict__ hout, __half* __restrict__ hs, int E2) {
    extern __shared__ char smraw[];
    float* sh   = (float*)(smraw + F_SH);
    float* sagg = (float*)(smraw + F_SAGG);
    float* sz   = (float*)(smraw + F_SZ);
    __half* ea  = (__half*)(smraw + F_EA);
    float* sWr  = (float*)(smraw + F_EA);   // reused after msg phase
    __half* w1h = (__half*)(smraw + F_W1H);
    float* sdeg = (float*)(smraw + F_SDEG);
    int* sse    = (int*)(smraw + F_SSE);
    int* sde    = (int*)(smraw + F_SDE);

    const int g = blockIdx.x;
    const int tid = threadIdx.x;
    const int w = tid >> 5;
    const int lane = tid & 31;
    const int nbase = g * NPG;

    // phase A: load h tile, zero agg, W1->fp16, zero deg
    for (int i = tid; i < NPG * HID; i += FTHREADS) {
        sh[i] = h[nbase * HID + i];
        sagg[i] = 0.f;
    }
    for (int i = tid; i < 128 * 32; i += FTHREADS)
        w1h[(i >> 5) * 40 + (i & 31)] = __float2half_rn(W1l[i]);
    if (tid < NPG) sdeg[tid] = 0.f;
    __syncthreads();

    // phase B: edge indices + degree
    if (tid < NEPG) {
        int k = tid;
        int ei = (k < NBR) ? g * NBR + k : E2 + g * NBR + (k - NBR);
        int s = src[ei] - nbase;
        int d = dst[ei] - nbase;
        sse[k] = s; sde[k] = d;
        atomicAdd(&sdeg[d], 1.0f);
    }
    __syncthreads();

    // phase C: build ea[96][136] fp16 = [h[src] | h[dst]] per edge row
    for (int i = tid; i < 96 * 128; i += FTHREADS) {
        int k = i >> 7, c = i & 127;
        float v = 0.f;
        if (k < NEPG) {
            int node = (c < 64) ? sse[k] : sde[k];
            v = sh[node * 64 + (c & 63)];
        }
        ea[k * 136 + c] = __float2half_rn(v);
    }
    __syncthreads();

    // phase D: z = ea @ W1 via WMMA; 12 warp-tiles (6m x 2n)
    if (w < 12) {
        int mt = w >> 1, nt = w & 1;
        wmma::fragment<wmma::accumulator, 16, 16, 16, float> acc;
        wmma::fill_fragment(acc, 0.f);
#pragma unroll
        for (int kk = 0; kk < 8; kk++) {
            wmma::fragment<wmma::matrix_a, 16, 16, 16, __half, wmma::row_major> af;
            wmma::fragment<wmma::matrix_b, 16, 16, 16, __half, wmma::row_major> bf;
            wmma::load_matrix_sync(af, ea + (mt * 16) * 136 + kk * 16, 136);
            wmma::load_matrix_sync(bf, w1h + (kk * 16) * 40 + nt * 16, 40);
            wmma::mma_sync(acc, af, bf, acc);
        }
        wmma::store_matrix_sync(sz + mt * 16 * 32 + nt * 16, acc, 32, wmma::mem_row_major);
    }
    __syncthreads();

    // phase E: bias + relu on z
    for (int i = tid; i < NEPG * 32; i += FTHREADS)
        sz[i] = fmaxf(sz[i] + b1l[i & 31], 0.f);
    __syncthreads();

    // phase F: msg gather (warp per edge), smem scatter
    const int c = lane & 7;    // o-chunk: outputs c*8 .. c*8+7
    const int jo = lane >> 3;  // j offset within group of 4
    for (int k = w; k < NEPG; k += FTHREADS / 32) {
        int s = sse[k], d = sde[k];
        const __half* Qs = Qh + (size_t)(nbase + s) * QCOLS;
        float zval = sz[k * 32 + lane];
        float acc[8];
#pragma unroll
        for (int i = 0; i < 8; i++) acc[i] = 0.f;
#pragma unroll
        for (int j0 = 0; j0 < 8; j0++) {
            int j = j0 * 4 + jo;
            float zz = __shfl_sync(0xffffffffu, zval, j);
            uint4 qv = *(const uint4*)(Qs + j * 64 + c * 8);
            const half2* qh = (const half2*)&qv;
#pragma unroll
            for (int i = 0; i < 4; i++) {
                float2 f = __half22float2(qh[i]);
                acc[2 * i] += zz * f.x;
                acc[2 * i + 1] += zz * f.y;
            }
        }
#pragma unroll
        for (int i = 0; i < 8; i++) {
            acc[i] += __shfl_xor_sync(0xffffffffu, acc[i], 8);
            acc[i] += __shfl_xor_sync(0xffffffffu, acc[i], 16);
        }
        int o = c * 8 + jo * 2;
        float2 bias = __half22float2(*(const half2*)(Qs + 2048 + o));
        atomicAdd(&sagg[d * 64 + o], acc[jo * 2] + bias.x);
        atomicAdd(&sagg[d * 64 + o + 1], acc[jo * 2 + 1] + bias.y);
    }
    __syncthreads();

    // phase G: load Wr (fp32) into the ea region
    for (int i = tid; i < 64 * 64; i += FTHREADS) sWr[i] = Wr[i];
    __syncthreads();

    // phase H: node update
    for (int i = tid; i < NPG * HID; i += FTHREADS) {
        int n = i >> 6, cc = i & 63;
        const float* hr = sh + n * 64;
        float acc = br[cc];
#pragma unroll
        for (int kk = 0; kk < 64; kk++) acc += hr[kk] * sWr[kk * 64 + cc];
        float h2 = sagg[i] / fmaxf(sdeg[n], 1.0f) + acc;
        float scale = gamma[cc] * rsqrtf(rvar[cc] + BN_EPS);
        h2 = (h2 - rmean[cc]) * scale + beta[cc];
        float r = fmaxf(h2, 0.f) + sh[i];
        hout[nbase * HID + i] = r;
        hs[nbase * HID + i] = __float2half_rn(r);
    }
}

// out[i] = relu([h[u]|h[v]] @ Wm1 + bm1) @ Wm2 + bm2 ; one warp per output row
__global__ void k_final(const float* __restrict__ h, const int* __restrict__ bu,
                        const int* __restrict__ bv, const float* __restrict__ Wm1,
                        const float* __restrict__ bm1, const float* __restrict__ Wm2,
                        const float* __restrict__ bm2, float* __restrict__ out,
                        int nout, int B, int npg) {
    int i = (blockIdx.x * blockDim.x + threadIdx.x) >> 5;
    int lane = threadIdx.x & 31;
    if (i >= nout) return;
    int g = i / B, b = i - g * B;
    int u = bu[b] + g * npg;
    int v = bv[b] + g * npg;
    const float* hu = h + (size_t)u * 64;
    const float* hv = h + (size_t)v * 64;
    float a0 = bm1[lane], a1 = bm1[lane + 32];
#pragma unroll
    for (int k = 0; k < 64; k++) {
        float x0 = hu[k];
        a0 += x0 * Wm1[k * 64 + lane];
        a1 += x0 * Wm1[k * 64 + lane + 32];
    }
#pragma unroll
    for (int k = 0; k < 64; k++) {
        float x1 = hv[k];
        a0 += x1 * Wm1[(64 + k) * 64 + lane];
        a1 += x1 * Wm1[(64 + k) * 64 + lane + 32];
    }
    float r = fmaxf(a0, 0.f) * Wm2[lane] + fmaxf(a1, 0.f) * Wm2[lane + 32];
#pragma unroll
    for (int off = 16; off; off >>= 1) r += __shfl_down_sync(0xffffffffu, r, off);
    if (lane == 0) out[i] = r + bm2[0];
}

extern "C" void kernel_launch(void* const* d_in, const int* in_sizes, int n_in,
                              void* d_out, int out_size) {
    const float* x   = (const float*)d_in[0];
    const int* eidx  = (const int*)d_in[1];
    const int* bu    = (const int*)d_in[2];
    const int* bv    = (const int*)d_in[3];
    int base = (in_sizes[4] == 1) ? 5 : 4;
    const float* Wp    = (const float*)d_in[base + 0];
    const float* bp    = (const float*)d_in[base + 1];
    const float* W1    = (const float*)d_in[base + 2];
    const float* b1    = (const float*)d_in[base + 3];
    const float* W2    = (const float*)d_in[base + 4];
    const float* b2    = (const float*)d_in[base + 5];
    const float* Wr    = (const float*)d_in[base + 6];
    const float* br    = (const float*)d_in[base + 7];
    const float* gamma = (const float*)d_in[base + 8];
    const float* beta  = (const float*)d_in[base + 9];
    const float* rmean = (const float*)d_in[base + 10];
    const float* rvar  = (const float*)d_in[base + 11];
    const float* Wm1   = (const float*)d_in[base + 12];
    const float* bm1   = (const float*)d_in[base + 13];
    const float* Wm2   = (const float*)d_in[base + 14];
    const float* bm2   = (const float*)d_in[base + 15];

    const int Nn = in_sizes[0] / 8;     // 15360
    const int E  = in_sizes[1] / 2;     // 41984
    const int B  = in_sizes[2];         // 41
    const int G  = out_size / B;        // 512
    const int npg = Nn / G;             // 30
    const int* src = eidx;
    const int* dst = eidx + E;
    const int E2 = E / 2;

    static float *p_h0 = nullptr, *p_h1;
    static __half *p_Q, *p_hs, *p_Ws;
    static const int SMEMB = (128 * APAD + 2 * 96 * BPAD) * sizeof(__half);
    if (!p_h0) {
        cudaGetSymbolAddress((void**)&p_h0, g_h0);
        cudaGetSymbolAddress((void**)&p_h1, g_h1);
        cudaGetSymbolAddress((void**)&p_Q, g_Q);
        cudaGetSymbolAddress((void**)&p_hs, g_hs);
        cudaGetSymbolAddress((void**)&p_Ws, g_Ws);
        cudaFuncSetAttribute(k_qwmma, cudaFuncAttributeMaxDynamicSharedMemorySize, SMEMB);
        cudaFuncSetAttribute(k_fused, cudaFuncAttributeMaxDynamicSharedMemorySize, F_TOT);
    }

    // launches: 0=proj, 1=wsplit a, 2=wsplit b, 3=qwmma(l0), 4=fused(l0),
    // 5=qwmma(l1) <- ncu -s 5 profiles the new k_qwmma
    const int WTOT = NLAYERS * QCOLS * HID;
    k_proj<<<(Nn * HID + 255) / 256, 256>>>(x, Wp, bp, p_h0, p_hs, Nn);
    k_wsplit<<<(WTOT / 2 + 255) / 256, 256>>>(W2, b2, p_Ws, 0, WTOT / 2);
    k_wsplit<<<(WTOT / 2 + 255) / 256, 256>>>(W2, b2, p_Ws, WTOT / 2, WTOT);

    float* cur = p_h0;
    float* nxt = p_h1;
    dim3 gq(QCOLS / 192, Nn / 128);
    for (int l = 0; l < NLAYERS; l++) {
        k_qwmma<<<gq, 256, SMEMB>>>(p_hs, p_Ws + (size_t)l * QCOLS * HID, p_Q);
        k_fused<<<G, FTHREADS, F_TOT>>>(cur, src, dst, p_Q,
                            W1 + (size_t)l * 128 * 32, b1 + (size_t)l * 32,
                            Wr + (size_t)l * 64 * 64, br + (size_t)l * 64,
                            gamma + (size_t)l * 64, beta + (size_t)l * 64,
                            rmean + (size_t)l * 64, rvar + (size_t)l * 64,
                            nxt, p_hs, E2);
        float* tmp = cur; cur = nxt; nxt = tmp;
    }
    k_final<<<(out_size + 7) / 8, 256>>>(cur, bu, bv, Wm1, bm1, Wm2, bm2,
                                         (float*)d_out, out_size, B, npg);
}

// round 13
// speedup vs baseline: 1.5085x; 1.1569x over previous
#include <cuda_runtime.h>
#include <cuda_fp16.h>
#include <mma.h>
#include <cstdint>

using namespace nvcuda;

// Problem constants (shapes fixed by the reference)
#define NNODES 15360       // 512 graphs * 30 nodes
#define HID 64
#define NPG 30             // nodes per graph
#define NBR 41             // branches per graph
#define NEPG 82            // edges per graph (bidirectional)
#define NLAYERS 5
#define QCOLS 2112         // 32*64 (w-part) + 64 (b2-part)
#define APAD 72            // padded smem stride for A (halfs)
#define BPAD 72            // padded smem stride for B (halfs)
#define FTHREADS 512       // k_fused block size
#define BN_EPS 1e-5f

// k_fused dynamic smem layout (bytes)
#define F_SH    0                    // float[1920]   h tile
#define F_SH16  7680                 // half[32*72]   fp16 h (padded)
#define F_SAGG  12288                // float[1920]   agg
#define F_SZ    19968                // float[96*32]  z
#define F_EA    32256                // half[96*136]  ea
#define F_W1H   58368                // half[128*40]  W1 fp16
#define F_WRH   68608                // half[64*72]   Wr fp16
#define F_RES   77824                // float[32*64]  R = h @ Wr
#define F_SDEG  86016                // float[30]
#define F_SSE   86136                // int[82]
#define F_SDE   86464                // int[82]
#define F_TOT   86792

// ---------------- scratch (device globals; no allocation allowed) -----------
__device__ float g_h0[NNODES * HID];
__device__ float g_h1[NNODES * HID];
__device__ __half g_Q[(size_t)NNODES * QCOLS];              // ~65 MB fp16
__device__ __half g_hs[(size_t)NNODES * HID];               // fp16 h
__device__ __half g_Ws[(size_t)NLAYERS * QCOLS * HID];      // B  [l][n][64] fp16

// ---------------- prep kernels ----------------------------------------------
// Ws[l][n][k] = fp16(W2p[k][n]); cols 0..2047 from W2, 2048..2111 from b2
__global__ void k_wsplit(const float* __restrict__ W2, const float* __restrict__ b2,
                         __half* __restrict__ Ws) {
    int idx = blockIdx.x * blockDim.x + threadIdx.x;
    const int total = NLAYERS * QCOLS * HID;
    if (idx >= total) return;
    int k = idx & 63;
    int n = (idx >> 6) % QCOLS;
    int l = idx / (QCOLS * HID);
    float v;
    if (n < 2048) {
        int j = n >> 6, o = n & 63;
        v = W2[(size_t)(l * 32 + j) * 4096 + k * 64 + o];
    } else {
        v = b2[(size_t)l * 4096 + k * 64 + (n - 2048)];
    }
    Ws[idx] = __float2half_rn(v);
}

// h0 = x @ Wp + bp  (+ fp16 copy of h0)
__global__ void k_proj(const float* __restrict__ x, const float* __restrict__ Wp,
                       const float* __restrict__ bp, float* __restrict__ h,
                       __half* __restrict__ hs, int N) {
    int t = blockIdx.x * blockDim.x + threadIdx.x;
    if (t >= N * HID) return;
    int n = t >> 6, c = t & 63;
    const float* xr = x + n * 8;
    float acc = bp[c];
#pragma unroll
    for (int k = 0; k < 8; k++) acc += xr[k] * Wp[k * 64 + c];
    h[t] = acc;
    hs[t] = __float2half_rn(acc);
}

// ---------------- WMMA fp16 GEMM: Q = h(15360x64) @ W^T(64x2112) -------------
// block: 128 M x (2 x 96) N subtiles; fp16 accum, direct global store.
__global__ __launch_bounds__(256, 3) void k_qwmma(const __half* __restrict__ A,
                                                  const __half* __restrict__ B,
                                                  __half* __restrict__ Q) {
    extern __shared__ __half sm[];
    __half* As = sm;                          // 128 x APAD
    __half* Bs = sm + 128 * APAD;             // 2 x (96 x BPAD)
    const int m0 = blockIdx.y * 128;
    const int n0 = blockIdx.x * 192;
    const int t = threadIdx.x;

    for (int i = t; i < 128 * 8; i += 256) {
        int r = i >> 3, c = (i & 7) * 8;
        *(uint4*)(As + r * APAD + c) = *(const uint4*)(A + (size_t)(m0 + r) * HID + c);
    }
    for (int i = t; i < 2 * 96 * 8; i += 256) {
        int s = i / 768;
        int r = (i % 768) >> 3, c = (i & 7) * 8;
        *(uint4*)(Bs + s * 96 * BPAD + r * BPAD + c) =
            *(const uint4*)(B + (size_t)(n0 + s * 96 + r) * HID + c);
    }
    __syncthreads();

    const int w = t >> 5;
    const int mw = (w & 3) * 32;
    const int nw = (w >> 2) * 48;

#pragma unroll
    for (int s = 0; s < 2; s++) {
        const __half* Bsub = Bs + s * 96 * BPAD;
        wmma::fragment<wmma::accumulator, 16, 16, 16, __half> acc[2][3];
#pragma unroll
        for (int i = 0; i < 2; i++)
#pragma unroll
            for (int j = 0; j < 3; j++) wmma::fill_fragment(acc[i][j], __float2half(0.f));

#pragma unroll
        for (int kk = 0; kk < 4; kk++) {
            wmma::fragment<wmma::matrix_b, 16, 16, 16, __half, wmma::col_major> bf[3];
#pragma unroll
            for (int j = 0; j < 3; j++)
                wmma::load_matrix_sync(bf[j], Bsub + (nw + j * 16) * BPAD + kk * 16, BPAD);
            wmma::fragment<wmma::matrix_a, 16, 16, 16, __half, wmma::row_major> af[2];
#pragma unroll
            for (int i = 0; i < 2; i++)
                wmma::load_matrix_sync(af[i], As + (mw + i * 16) * APAD + kk * 16, APAD);
#pragma unroll
            for (int i = 0; i < 2; i++)
#pragma unroll
                for (int j = 0; j < 3; j++)
                    wmma::mma_sync(acc[i][j], af[i], bf[j], acc[i][j]);
        }

        // epilogue: store fp16 accumulators straight to global
#pragma unroll
        for (int i = 0; i < 2; i++)
#pragma unroll
            for (int j = 0; j < 3; j++)
                wmma::store_matrix_sync(
                    Q + (size_t)(m0 + mw + i * 16) * QCOLS + n0 + s * 96 + nw + j * 16,
                    acc[i][j], QCOLS, wmma::mem_row_major);
    }
}

// ---------------- fused per-graph layer kernel --------------------------------
// z + R via WMMA (concurrent warps), msg gather, smem scatter, node update
__global__ __launch_bounds__(FTHREADS, 2) void k_fused(
    const float* __restrict__ h, const int* __restrict__ src, const int* __restrict__ dst,
    const __half* __restrict__ Qh, const float* __restrict__ W1l, const float* __restrict__ b1l,
    const float* __restrict__ Wr, const float* __restrict__ br,
    const float* __restrict__ gamma, const float* __restrict__ beta,
    const float* __restrict__ rmean, const float* __restrict__ rvar,
    float* __restrict__ hout, __half* __restrict__ hs, int E2) {
    extern __shared__ char smraw[];
    float* sh    = (float*)(smraw + F_SH);
    __half* sh16 = (__half*)(smraw + F_SH16);
    float* sagg  = (float*)(smraw + F_SAGG);
    float* sz    = (float*)(smraw + F_SZ);
    __half* ea   = (__half*)(smraw + F_EA);
    __half* w1h  = (__half*)(smraw + F_W1H);
    __half* wrh  = (__half*)(smraw + F_WRH);
    float* Rbuf  = (float*)(smraw + F_RES);
    float* sdeg  = (float*)(smraw + F_SDEG);
    int* sse     = (int*)(smraw + F_SSE);
    int* sde     = (int*)(smraw + F_SDE);

    const int g = blockIdx.x;
    const int tid = threadIdx.x;
    const int w = tid >> 5;
    const int lane = tid & 31;
    const int nbase = g * NPG;

    // phase A: stage h (fp32 + fp16), weights (W1, Wr fp16), zero agg/deg,
    // load edge indices (degree atomics deferred past the sync — no race)
    for (int i = tid; i < NPG * HID; i += FTHREADS) {
        float v = h[nbase * HID + i];
        sh[i] = v;
        sagg[i] = 0.f;
    }
    for (int i = tid; i < 32 * 72; i += FTHREADS) {
        int r = i / 72, c = i - r * 72;
        __half v = __float2half_rn(0.f);
        if (r < NPG && c < 64) v = __float2half_rn(h[nbase * HID + r * 64 + c]);
        sh16[i] = v;
    }
    for (int i = tid; i < 128 * 32; i += FTHREADS)
        w1h[(i >> 5) * 40 + (i & 31)] = __float2half_rn(W1l[i]);
    for (int i = tid; i < 64 * 64; i += FTHREADS)
        wrh[(i >> 6) * 72 + (i & 63)] = __float2half_rn(Wr[i]);
    if (tid < NPG) sdeg[tid] = 0.f;
    if (tid >= 128 && tid < 128 + NEPG) {
        int k = tid - 128;
        int ei = (k < NBR) ? g * NBR + k : E2 + g * NBR + (k - NBR);
        sse[k] = src[ei] - nbase;
        sde[k] = dst[ei] - nbase;
    }
    __syncthreads();

    // phase C: degree atomics (sdeg now safely zeroed) + build ea[96][136]
    if (tid < NEPG) atomicAdd(&sdeg[sde[tid]], 1.0f);
    for (int i = tid; i < 96 * 128; i += FTHREADS) {
        int k = i >> 7, c = i & 127;
        float v = 0.f;
        if (k < NEPG) {
            int node = (c < 64) ? sse[k] : sde[k];
            v = sh[node * 64 + (c & 63)];
        }
        ea[k * 136 + c] = __float2half_rn(v);
    }
    __syncthreads();

    // phase D: warps 0-11: z = ea @ W1 (12 tiles); warps 12-15: R = h @ Wr (8 tiles)
    if (w < 12) {
        int mt = w >> 1, nt = w & 1;
        wmma::fragment<wmma::accumulator, 16, 16, 16, float> acc;
        wmma::fill_fragment(acc, 0.f);
#pragma unroll
        for (int kk = 0; kk < 8; kk++) {
            wmma::fragment<wmma::matrix_a, 16, 16, 16, __half, wmma::row_major> af;
            wmma::fragment<wmma::matrix_b, 16, 16, 16, __half, wmma::row_major> bf;
            wmma::load_matrix_sync(af, ea + (mt * 16) * 136 + kk * 16, 136);
            wmma::load_matrix_sync(bf, w1h + (kk * 16) * 40 + nt * 16, 40);
            wmma::mma_sync(acc, af, bf, acc);
        }
        wmma::store_matrix_sync(sz + mt * 16 * 32 + nt * 16, acc, 32, wmma::mem_row_major);
    } else {
#pragma unroll
        for (int rep = 0; rep < 2; rep++) {
            int T = (w - 12) + rep * 4;      // 0..7
            int mt = T >> 2, nt = T & 3;
            wmma::fragment<wmma::accumulator, 16, 16, 16, float> acc;
            wmma::fill_fragment(acc, 0.f);
#pragma unroll
            for (int kk = 0; kk < 4; kk++) {
                wmma::fragment<wmma::matrix_a, 16, 16, 16, __half, wmma::row_major> af;
                wmma::fragment<wmma::matrix_b, 16, 16, 16, __half, wmma::row_major> bf;
                wmma::load_matrix_sync(af, sh16 + (mt * 16) * 72 + kk * 16, 72);
                wmma::load_matrix_sync(bf, wrh + (kk * 16) * 72 + nt * 16, 72);
                wmma::mma_sync(acc, af, bf, acc);
            }
            wmma::store_matrix_sync(Rbuf + mt * 16 * 64 + nt * 16, acc, 64,
                                    wmma::mem_row_major);
        }
    }
    __syncthreads();

    // phase F: msg gather (warp per edge), bias+relu on z folded in
    const int c = lane & 7;    // o-chunk: outputs c*8 .. c*8+7
    const int jo = lane >> 3;  // j offset within group of 4
    const float b1v = b1l[lane];
    for (int k = w; k < NEPG; k += FTHREADS / 32) {
        int s = sse[k], d = sde[k];
        const __half* Qs = Qh + (size_t)(nbase + s) * QCOLS;
        float zval = fmaxf(sz[k * 32 + lane] + b1v, 0.f);
        float acc[8];
#pragma unroll
        for (int i = 0; i < 8; i++) acc[i] = 0.f;
#pragma unroll
        for (int j0 = 0; j0 < 8; j0++) {
            int j = j0 * 4 + jo;
            float zz = __shfl_sync(0xffffffffu, zval, j);
            uint4 qv = *(const uint4*)(Qs + j * 64 + c * 8);
            const half2* qh = (const half2*)&qv;
#pragma unroll
            for (int i = 0; i < 4; i++) {
                float2 f = __half22float2(qh[i]);
                acc[2 * i] += zz * f.x;
                acc[2 * i + 1] += zz * f.y;
            }
        }
#pragma unroll
        for (int i = 0; i < 8; i++) {
            acc[i] += __shfl_xor_sync(0xffffffffu, acc[i], 8);
            acc[i] += __shfl_xor_sync(0xffffffffu, acc[i], 16);
        }
        int o = c * 8 + jo * 2;
        float2 bias = __half22float2(*(const half2*)(Qs + 2048 + o));
        atomicAdd(&sagg[d * 64 + o], acc[jo * 2] + bias.x);
        atomicAdd(&sagg[d * 64 + o + 1], acc[jo * 2 + 1] + bias.y);
    }
    __syncthreads();

    // phase H: elementwise node update (root GEMM already in Rbuf)
    for (int i = tid; i < NPG * HID; i += FTHREADS) {
        int n = i >> 6, cc = i & 63;
        float h2 = sagg[i] / fmaxf(sdeg[n], 1.0f) + Rbuf[n * 64 + cc] + br[cc];
        float scale = gamma[cc] * rsqrtf(rvar[cc] + BN_EPS);
        h2 = (h2 - rmean[cc]) * scale + beta[cc];
        float r = fmaxf(h2, 0.f) + sh[i];
        hout[nbase * HID + i] = r;
        hs[nbase * HID + i] = __float2half_rn(r);
    }
}

// out[i] = relu([h[u]|h[v]] @ Wm1 + bm1) @ Wm2 + bm2 ; one warp per output row
__global__ void k_final(const float* __restrict__ h, const int* __restrict__ bu,
                        const int* __restrict__ bv, const float* __restrict__ Wm1,
                        const float* __restrict__ bm1, const float* __restrict__ Wm2,
                        const float* __restrict__ bm2, float* __restrict__ out,
                        int nout, int B, int npg) {
    int i = (blockIdx.x * blockDim.x + threadIdx.x) >> 5;
    int lane = threadIdx.x & 31;
    if (i >= nout) return;
    int g = i / B, b = i - g * B;
    int u = bu[b] + g * npg;
    int v = bv[b] + g * npg;
    const float* hu = h + (size_t)u * 64;
    const float* hv = h + (size_t)v * 64;
    float a0 = bm1[lane], a1 = bm1[lane + 32];
#pragma unroll
    for (int k = 0; k < 64; k++) {
        float x0 = hu[k];
        a0 += x0 * Wm1[k * 64 + lane];
        a1 += x0 * Wm1[k * 64 + lane + 32];
    }
#pragma unroll
    for (int k = 0; k < 64; k++) {
        float x1 = hv[k];
        a0 += x1 * Wm1[(64 + k) * 64 + lane];
        a1 += x1 * Wm1[(64 + k) * 64 + lane + 32];
    }
    float r = fmaxf(a0, 0.f) * Wm2[lane] + fmaxf(a1, 0.f) * Wm2[lane + 32];
#pragma unroll
    for (int off = 16; off; off >>= 1) r += __shfl_down_sync(0xffffffffu, r, off);
    if (lane == 0) out[i] = r + bm2[0];
}

extern "C" void kernel_launch(void* const* d_in, const int* in_sizes, int n_in,
                              void* d_out, int out_size) {
    const float* x   = (const float*)d_in[0];
    const int* eidx  = (const int*)d_in[1];
    const int* bu    = (const int*)d_in[2];
    const int* bv    = (const int*)d_in[3];
    int base = (in_sizes[4] == 1) ? 5 : 4;
    const float* Wp    = (const float*)d_in[base + 0];
    const float* bp    = (const float*)d_in[base + 1];
    const float* W1    = (const float*)d_in[base + 2];
    const float* b1    = (const float*)d_in[base + 3];
    const float* W2    = (const float*)d_in[base + 4];
    const float* b2    = (const float*)d_in[base + 5];
    const float* Wr    = (const float*)d_in[base + 6];
    const float* br    = (const float*)d_in[base + 7];
    const float* gamma = (const float*)d_in[base + 8];
    const float* beta  = (const float*)d_in[base + 9];
    const float* rmean = (const float*)d_in[base + 10];
    const float* rvar  = (const float*)d_in[base + 11];
    const float* Wm1   = (const float*)d_in[base + 12];
    const float* bm1   = (const float*)d_in[base + 13];
    const float* Wm2   = (const float*)d_in[base + 14];
    const float* bm2   = (const float*)d_in[base + 15];

    const int Nn = in_sizes[0] / 8;     // 15360
    const int E  = in_sizes[1] / 2;     // 41984
    const int B  = in_sizes[2];         // 41
    const int G  = out_size / B;        // 512
    const int npg = Nn / G;             // 30
    const int* src = eidx;
    const int* dst = eidx + E;
    const int E2 = E / 2;

    static float *p_h0 = nullptr, *p_h1;
    static __half *p_Q, *p_hs, *p_Ws;
    static const int SMEMB = (128 * APAD + 2 * 96 * BPAD) * sizeof(__half);
    if (!p_h0) {
        cudaGetSymbolAddress((void**)&p_h0, g_h0);
        cudaGetSymbolAddress((void**)&p_h1, g_h1);
        cudaGetSymbolAddress((void**)&p_Q, g_Q);
        cudaGetSymbolAddress((void**)&p_hs, g_hs);
        cudaGetSymbolAddress((void**)&p_Ws, g_Ws);
        cudaFuncSetAttribute(k_qwmma, cudaFuncAttributeMaxDynamicSharedMemorySize, SMEMB);
        cudaFuncSetAttribute(k_fused, cudaFuncAttributeMaxDynamicSharedMemorySize, F_TOT);
    }

    // launches: 0=proj, 1=wsplit, 2=qwmma(l0), 3=fused(l0), 4=qwmma(l1),
    // 5=fused(l1) <- ncu -s 5 profiles the new k_fused
    const int WTOT = NLAYERS * QCOLS * HID;
    k_proj<<<(Nn * HID + 255) / 256, 256>>>(x, Wp, bp, p_h0, p_hs, Nn);
    k_wsplit<<<(WTOT + 255) / 256, 256>>>(W2, b2, p_Ws);

    float* cur = p_h0;
    float* nxt = p_h1;
    dim3 gq(QCOLS / 192, Nn / 128);
    for (int l = 0; l < NLAYERS; l++) {
        k_qwmma<<<gq, 256, SMEMB>>>(p_hs, p_Ws + (size_t)l * QCOLS * HID, p_Q);
        k_fused<<<G, FTHREADS, F_TOT>>>(cur, src, dst, p_Q,
                            W1 + (size_t)l * 128 * 32, b1 + (size_t)l * 32,
                            Wr + (size_t)l * 64 * 64, br + (size_t)l * 64,
                            gamma + (size_t)l * 64, beta + (size_t)l * 64,
                            rmean + (size_t)l * 64, rvar + (size_t)l * 64,
                            nxt, p_hs, E2);
        float* tmp = cur; cur = nxt; nxt = tmp;
    }
    k_final<<<(out_size + 7) / 8, 256>>>(cur, bu, bv, Wm1, bm1, Wm2, bm2,
                                         (float*)d_out, out_size, B, npg);
}

// round 14
// speedup vs baseline: 1.5164x; 1.0052x over previous
#include <cuda_runtime.h>
#include <cuda_fp16.h>
#include <mma.h>
#include <cstdint>

using namespace nvcuda;

// Problem constants (shapes fixed by the reference)
#define NNODES 15360       // 512 graphs * 30 nodes
#define HID 64
#define NPG 30             // nodes per graph
#define NBR 41             // branches per graph
#define NEPG 82            // edges per graph (bidirectional)
#define NLAYERS 5
#define QCOLS 2112         // 32*64 (w-part) + 64 (b2-part)
#define APAD 72            // padded smem stride for A (halfs)
#define BPAD 72            // padded smem stride for B (halfs)
#define FTHREADS 512       // k_fused block size
#define BN_EPS 1e-5f

// k_fused dynamic smem layout (bytes)
#define F_SH    0                    // float[1920]   h tile
#define F_SH16  7680                 // half[32*72]   fp16 h (padded)
#define F_SAGG  12288                // float[1920]   agg
#define F_SZ    19968                // float[96*32]  z
#define F_EA    32256                // half[96*136]  ea
#define F_W1H   58368                // half[128*40]  W1 fp16
#define F_WRH   68608                // half[64*72]   Wr fp16
#define F_RES   77824                // float[32*64]  R = h @ Wr
#define F_SDEG  86016                // float[30]
#define F_SSE   86136                // int[82]
#define F_SDE   86464                // int[82]
#define F_TOT   86792

// ---------------- scratch (device globals; no allocation allowed) -----------
__device__ float g_h0[NNODES * HID];
__device__ float g_h1[NNODES * HID];
__device__ __half g_Q[(size_t)NNODES * QCOLS];              // ~65 MB fp16
__device__ __half g_hs[(size_t)NNODES * HID];               // fp16 h
__device__ __half g_Ws[(size_t)NLAYERS * QCOLS * HID];      // B  [l][n][64] fp16

// ---------------- prep kernels ----------------------------------------------
// Ws[l][n][k] = fp16(W2p[k][n]); cols 0..2047 from W2, 2048..2111 from b2
__global__ void k_wsplit(const float* __restrict__ W2, const float* __restrict__ b2,
                         __half* __restrict__ Ws, int lo0, int hi0) {
    int idx = lo0 + blockIdx.x * blockDim.x + threadIdx.x;
    if (idx >= hi0) return;
    int k = idx & 63;
    int n = (idx >> 6) % QCOLS;
    int l = idx / (QCOLS * HID);
    float v;
    if (n < 2048) {
        int j = n >> 6, o = n & 63;
        v = W2[(size_t)(l * 32 + j) * 4096 + k * 64 + o];
    } else {
        v = b2[(size_t)l * 4096 + k * 64 + (n - 2048)];
    }
    Ws[idx] = __float2half_rn(v);
}

// h0 = x @ Wp + bp  (+ fp16 copy of h0)
__global__ void k_proj(const float* __restrict__ x, const float* __restrict__ Wp,
                       const float* __restrict__ bp, float* __restrict__ h,
                       __half* __restrict__ hs, int N) {
    int t = blockIdx.x * blockDim.x + threadIdx.x;
    if (t >= N * HID) return;
    int n = t >> 6, c = t & 63;
    const float* xr = x + n * 8;
    float acc = bp[c];
#pragma unroll
    for (int k = 0; k < 8; k++) acc += xr[k] * Wp[k * 64 + c];
    h[t] = acc;
    hs[t] = __float2half_rn(acc);
}

// ---------------- WMMA fp16 GEMM: Q = h(15360x64) @ W^T(64x2112) -------------
// block: 128 M x (2 x 96) N subtiles; fp16 accum, direct global store.
// 4 CTAs/SM (reg-capped at 64) for latency hiding.
__global__ __launch_bounds__(256, 4) void k_qwmma(const __half* __restrict__ A,
                                                  const __half* __restrict__ B,
                                                  __half* __restrict__ Q) {
    extern __shared__ __half sm[];
    __half* As = sm;                          // 128 x APAD
    __half* Bs = sm + 128 * APAD;             // 2 x (96 x BPAD)
    const int m0 = blockIdx.y * 128;
    const int n0 = blockIdx.x * 192;
    const int t = threadIdx.x;

    for (int i = t; i < 128 * 8; i += 256) {
        int r = i >> 3, c = (i & 7) * 8;
        *(uint4*)(As + r * APAD + c) = *(const uint4*)(A + (size_t)(m0 + r) * HID + c);
    }
    for (int i = t; i < 2 * 96 * 8; i += 256) {
        int s = i / 768;
        int r = (i % 768) >> 3, c = (i & 7) * 8;
        *(uint4*)(Bs + s * 96 * BPAD + r * BPAD + c) =
            *(const uint4*)(B + (size_t)(n0 + s * 96 + r) * HID + c);
    }
    __syncthreads();

    const int w = t >> 5;
    const int mw = (w & 3) * 32;
    const int nw = (w >> 2) * 48;

#pragma unroll
    for (int s = 0; s < 2; s++) {
        const __half* Bsub = Bs + s * 96 * BPAD;
        wmma::fragment<wmma::accumulator, 16, 16, 16, __half> acc[2][3];
#pragma unroll
        for (int i = 0; i < 2; i++)
#pragma unroll
            for (int j = 0; j < 3; j++) wmma::fill_fragment(acc[i][j], __float2half(0.f));

#pragma unroll
        for (int kk = 0; kk < 4; kk++) {
            wmma::fragment<wmma::matrix_b, 16, 16, 16, __half, wmma::col_major> bf[3];
#pragma unroll
            for (int j = 0; j < 3; j++)
                wmma::load_matrix_sync(bf[j], Bsub + (nw + j * 16) * BPAD + kk * 16, BPAD);
            wmma::fragment<wmma::matrix_a, 16, 16, 16, __half, wmma::row_major> af[2];
#pragma unroll
            for (int i = 0; i < 2; i++)
                wmma::load_matrix_sync(af[i], As + (mw + i * 16) * APAD + kk * 16, APAD);
#pragma unroll
            for (int i = 0; i < 2; i++)
#pragma unroll
                for (int j = 0; j < 3; j++)
                    wmma::mma_sync(acc[i][j], af[i], bf[j], acc[i][j]);
        }

        // epilogue: store fp16 accumulators straight to global
#pragma unroll
        for (int i = 0; i < 2; i++)
#pragma unroll
            for (int j = 0; j < 3; j++)
                wmma::store_matrix_sync(
                    Q + (size_t)(m0 + mw + i * 16) * QCOLS + n0 + s * 96 + nw + j * 16,
                    acc[i][j], QCOLS, wmma::mem_row_major);
    }
}

// ---------------- fused per-graph layer kernel --------------------------------
// z + R via WMMA (concurrent warps), msg gather, smem scatter, node update
__global__ __launch_bounds__(FTHREADS, 2) void k_fused(
    const float* __restrict__ h, const int* __restrict__ src, const int* __restrict__ dst,
    const __half* __restrict__ Qh, const float* __restrict__ W1l, const float* __restrict__ b1l,
    const float* __restrict__ Wr, const float* __restrict__ br,
    const float* __restrict__ gamma, const float* __restrict__ beta,
    const float* __restrict__ rmean, const float* __restrict__ rvar,
    float* __restrict__ hout, __half* __restrict__ hs, int E2) {
    extern __shared__ char smraw[];
    float* sh    = (float*)(smraw + F_SH);
    __half* sh16 = (__half*)(smraw + F_SH16);
    float* sagg  = (float*)(smraw + F_SAGG);
    float* sz    = (float*)(smraw + F_SZ);
    __half* ea   = (__half*)(smraw + F_EA);
    __half* w1h  = (__half*)(smraw + F_W1H);
    __half* wrh  = (__half*)(smraw + F_WRH);
    float* Rbuf  = (float*)(smraw + F_RES);
    float* sdeg  = (float*)(smraw + F_SDEG);
    int* sse     = (int*)(smraw + F_SSE);
    int* sde     = (int*)(smraw + F_SDE);

    const int g = blockIdx.x;
    const int tid = threadIdx.x;
    const int w = tid >> 5;
    const int lane = tid & 31;
    const int nbase = g * NPG;

    // phase A: stage h (fp32 + fp16), weights (W1, Wr fp16), zero agg/deg,
    // load edge indices (degree atomics deferred past the sync — no race)
    for (int i = tid; i < NPG * HID; i += FTHREADS) {
        float v = h[nbase * HID + i];
        sh[i] = v;
        sagg[i] = 0.f;
    }
    for (int i = tid; i < 32 * 72; i += FTHREADS) {
        int r = i / 72, c = i - r * 72;
        __half v = __float2half_rn(0.f);
        if (r < NPG && c < 64) v = __float2half_rn(h[nbase * HID + r * 64 + c]);
        sh16[i] = v;
    }
    for (int i = tid; i < 128 * 32; i += FTHREADS)
        w1h[(i >> 5) * 40 + (i & 31)] = __float2half_rn(W1l[i]);
    for (int i = tid; i < 64 * 64; i += FTHREADS)
        wrh[(i >> 6) * 72 + (i & 63)] = __float2half_rn(Wr[i]);
    if (tid < NPG) sdeg[tid] = 0.f;
    if (tid >= 128 && tid < 128 + NEPG) {
        int k = tid - 128;
        int ei = (k < NBR) ? g * NBR + k : E2 + g * NBR + (k - NBR);
        sse[k] = src[ei] - nbase;
        sde[k] = dst[ei] - nbase;
    }
    __syncthreads();

    // phase C: degree atomics (sdeg now safely zeroed) + build ea[96][136]
    if (tid < NEPG) atomicAdd(&sdeg[sde[tid]], 1.0f);
    for (int i = tid; i < 96 * 128; i += FTHREADS) {
        int k = i >> 7, c = i & 127;
        float v = 0.f;
        if (k < NEPG) {
            int node = (c < 64) ? sse[k] : sde[k];
            v = sh[node * 64 + (c & 63)];
        }
        ea[k * 136 + c] = __float2half_rn(v);
    }
    __syncthreads();

    // phase D: warps 0-11: z = ea @ W1 (12 tiles); warps 12-15: R = h @ Wr (8 tiles)
    if (w < 12) {
        int mt = w >> 1, nt = w & 1;
        wmma::fragment<wmma::accumulator, 16, 16, 16, float> acc;
        wmma::fill_fragment(acc, 0.f);
#pragma unroll
        for (int kk = 0; kk < 8; kk++) {
            wmma::fragment<wmma::matrix_a, 16, 16, 16, __half, wmma::row_major> af;
            wmma::fragment<wmma::matrix_b, 16, 16, 16, __half, wmma::row_major> bf;
            wmma::load_matrix_sync(af, ea + (mt * 16) * 136 + kk * 16, 136);
            wmma::load_matrix_sync(bf, w1h + (kk * 16) * 40 + nt * 16, 40);
            wmma::mma_sync(acc, af, bf, acc);
        }
        wmma::store_matrix_sync(sz + mt * 16 * 32 + nt * 16, acc, 32, wmma::mem_row_major);
    } else {
#pragma unroll
        for (int rep = 0; rep < 2; rep++) {
            int T = (w - 12) + rep * 4;      // 0..7
            int mt = T >> 2, nt = T & 3;
            wmma::fragment<wmma::accumulator, 16, 16, 16, float> acc;
            wmma::fill_fragment(acc, 0.f);
#pragma unroll
            for (int kk = 0; kk < 4; kk++) {
                wmma::fragment<wmma::matrix_a, 16, 16, 16, __half, wmma::row_major> af;
                wmma::fragment<wmma::matrix_b, 16, 16, 16, __half, wmma::row_major> bf;
                wmma::load_matrix_sync(af, sh16 + (mt * 16) * 72 + kk * 16, 72);
                wmma::load_matrix_sync(bf, wrh + (kk * 16) * 72 + nt * 16, 72);
                wmma::mma_sync(acc, af, bf, acc);
            }
            wmma::store_matrix_sync(Rbuf + mt * 16 * 64 + nt * 16, acc, 64,
                                    wmma::mem_row_major);
        }
    }
    __syncthreads();

    // phase F: msg gather (warp per edge), bias+relu on z folded in
    const int c = lane & 7;    // o-chunk: outputs c*8 .. c*8+7
    const int jo = lane >> 3;  // j offset within group of 4
    const float b1v = b1l[lane];
    for (int k = w; k < NEPG; k += FTHREADS / 32) {
        int s = sse[k], d = sde[k];
        const __half* Qs = Qh + (size_t)(nbase + s) * QCOLS;
        float zval = fmaxf(sz[k * 32 + lane] + b1v, 0.f);
        float acc[8];
#pragma unroll
        for (int i = 0; i < 8; i++) acc[i] = 0.f;
#pragma unroll
        for (int j0 = 0; j0 < 8; j0++) {
            int j = j0 * 4 + jo;
            float zz = __shfl_sync(0xffffffffu, zval, j);
            uint4 qv = *(const uint4*)(Qs + j * 64 + c * 8);
            const half2* qh = (const half2*)&qv;
#pragma unroll
            for (int i = 0; i < 4; i++) {
                float2 f = __half22float2(qh[i]);
                acc[2 * i] += zz * f.x;
                acc[2 * i + 1] += zz * f.y;
            }
        }
#pragma unroll
        for (int i = 0; i < 8; i++) {
            acc[i] += __shfl_xor_sync(0xffffffffu, acc[i], 8);
            acc[i] += __shfl_xor_sync(0xffffffffu, acc[i], 16);
        }
        int o = c * 8 + jo * 2;
        float2 bias = __half22float2(*(const half2*)(Qs + 2048 + o));
        atomicAdd(&sagg[d * 64 + o], acc[jo * 2] + bias.x);
        atomicAdd(&sagg[d * 64 + o + 1], acc[jo * 2 + 1] + bias.y);
    }
    __syncthreads();

    // phase H: elementwise node update (root GEMM already in Rbuf)
    for (int i = tid; i < NPG * HID; i += FTHREADS) {
        int n = i >> 6, cc = i & 63;
        float h2 = sagg[i] / fmaxf(sdeg[n], 1.0f) + Rbuf[n * 64 + cc] + br[cc];
        float scale = gamma[cc] * rsqrtf(rvar[cc] + BN_EPS);
        h2 = (h2 - rmean[cc]) * scale + beta[cc];
        float r = fmaxf(h2, 0.f) + sh[i];
        hout[nbase * HID + i] = r;
        hs[nbase * HID + i] = __float2half_rn(r);
    }
}

// out[i] = relu([h[u]|h[v]] @ Wm1 + bm1) @ Wm2 + bm2 ; one warp per output row
__global__ void k_final(const float* __restrict__ h, const int* __restrict__ bu,
                        const int* __restrict__ bv, const float* __restrict__ Wm1,
                        const float* __restrict__ bm1, const float* __restrict__ Wm2,
                        const float* __restrict__ bm2, float* __restrict__ out,
                        int nout, int B, int npg) {
    int i = (blockIdx.x * blockDim.x + threadIdx.x) >> 5;
    int lane = threadIdx.x & 31;
    if (i >= nout) return;
    int g = i / B, b = i - g * B;
    int u = bu[b] + g * npg;
    int v = bv[b] + g * npg;
    const float* hu = h + (size_t)u * 64;
    const float* hv = h + (size_t)v * 64;
    float a0 = bm1[lane], a1 = bm1[lane + 32];
#pragma unroll
    for (int k = 0; k < 64; k++) {
        float x0 = hu[k];
        a0 += x0 * Wm1[k * 64 + lane];
        a1 += x0 * Wm1[k * 64 + lane + 32];
    }
#pragma unroll
    for (int k = 0; k < 64; k++) {
        float x1 = hv[k];
        a0 += x1 * Wm1[(64 + k) * 64 + lane];
        a1 += x1 * Wm1[(64 + k) * 64 + lane + 32];
    }
    float r = fmaxf(a0, 0.f) * Wm2[lane] + fmaxf(a1, 0.f) * Wm2[lane + 32];
#pragma unroll
    for (int off = 16; off; off >>= 1) r += __shfl_down_sync(0xffffffffu, r, off);
    if (lane == 0) out[i] = r + bm2[0];
}

extern "C" void kernel_launch(void* const* d_in, const int* in_sizes, int n_in,
                              void* d_out, int out_size) {
    const float* x   = (const float*)d_in[0];
    const int* eidx  = (const int*)d_in[1];
    const int* bu    = (const int*)d_in[2];
    const int* bv    = (const int*)d_in[3];
    int base = (in_sizes[4] == 1) ? 5 : 4;
    const float* Wp    = (const float*)d_in[base + 0];
    const float* bp    = (const float*)d_in[base + 1];
    const float* W1    = (const float*)d_in[base + 2];
    const float* b1    = (const float*)d_in[base + 3];
    const float* W2    = (const float*)d_in[base + 4];
    const float* b2    = (const float*)d_in[base + 5];
    const float* Wr    = (const float*)d_in[base + 6];
    const float* br    = (const float*)d_in[base + 7];
    const float* gamma = (const float*)d_in[base + 8];
    const float* beta  = (const float*)d_in[base + 9];
    const float* rmean = (const float*)d_in[base + 10];
    const float* rvar  = (const float*)d_in[base + 11];
    const float* Wm1   = (const float*)d_in[base + 12];
    const float* bm1   = (const float*)d_in[base + 13];
    const float* Wm2   = (const float*)d_in[base + 14];
    const float* bm2   = (const float*)d_in[base + 15];

    const int Nn = in_sizes[0] / 8;     // 15360
    const int E  = in_sizes[1] / 2;     // 41984
    const int B  = in_sizes[2];         // 41
    const int G  = out_size / B;        // 512
    const int npg = Nn / G;             // 30
    const int* src = eidx;
    const int* dst = eidx + E;
    const int E2 = E / 2;

    static float *p_h0 = nullptr, *p_h1;
    static __half *p_Q, *p_hs, *p_Ws;
    static const int SMEMB = (128 * APAD + 2 * 96 * BPAD) * sizeof(__half);
    if (!p_h0) {
        cudaGetSymbolAddress((void**)&p_h0, g_h0);
        cudaGetSymbolAddress((void**)&p_h1, g_h1);
        cudaGetSymbolAddress((void**)&p_Q, g_Q);
        cudaGetSymbolAddress((void**)&p_hs, g_hs);
        cudaGetSymbolAddress((void**)&p_Ws, g_Ws);
        cudaFuncSetAttribute(k_qwmma, cudaFuncAttributeMaxDynamicSharedMemorySize, SMEMB);
        cudaFuncSetAttribute(k_fused, cudaFuncAttributeMaxDynamicSharedMemorySize, F_TOT);
    }

    // launches: 0=proj, 1=wsplitA, 2=wsplitB, 3=qwmma(l0), 4=fused(l0),
    // 5=qwmma(l1) <- ncu -s 5 profiles k_qwmma (verify occupancy theory)
    const int WTOT = NLAYERS * QCOLS * HID;
    k_proj<<<(Nn * HID + 255) / 256, 256>>>(x, Wp, bp, p_h0, p_hs, Nn);
    k_wsplit<<<(WTOT / 2 + 255) / 256, 256>>>(W2, b2, p_Ws, 0, WTOT / 2);
    k_wsplit<<<(WTOT / 2 + 255) / 256, 256>>>(W2, b2, p_Ws, WTOT / 2, WTOT);

    float* cur = p_h0;
    float* nxt = p_h1;
    dim3 gq(QCOLS / 192, Nn / 128);
    for (int l = 0; l < NLAYERS; l++) {
        k_qwmma<<<gq, 256, SMEMB>>>(p_hs, p_Ws + (size_t)l * QCOLS * HID, p_Q);
        k_fused<<<G, FTHREADS, F_TOT>>>(cur, src, dst, p_Q,
                            W1 + (size_t)l * 128 * 32, b1 + (size_t)l * 32,
                            Wr + (size_t)l * 64 * 64, br + (size_t)l * 64,
                            gamma + (size_t)l * 64, beta + (size_t)l * 64,
                            rmean + (size_t)l * 64, rvar + (size_t)l * 64,
                            nxt, p_hs, E2);
        float* tmp = cur; cur = nxt; nxt = tmp;
    }
    k_final<<<(out_size + 7) / 8, 256>>>(cur, bu, bv, Wm1, bm1, Wm2, bm2,
                                         (float*)d_out, out_size, B, npg);
}

// round 15
// speedup vs baseline: 1.5812x; 1.0427x over previous
#include <cuda_runtime.h>
#include <cuda_fp16.h>
#include <mma.h>
#include <cstdint>

using namespace nvcuda;

// Problem constants (shapes fixed by the reference)
#define NNODES 15360       // 512 graphs * 30 nodes
#define HID 64
#define NPG 30             // nodes per graph
#define NBR 41             // branches per graph
#define NEPG 82            // edges per graph (bidirectional)
#define NLAYERS 5
#define QCOLS 2112         // 32*64 (w-part) + 64 (b2-part)
#define APAD 72            // padded smem stride for A (halfs)
#define BPAD 72            // padded smem stride for B (halfs)
#define OPAD 200           // padded smem stride for output stage (halfs, 400B)
#define FTHREADS 512       // k_fused block size
#define BN_EPS 1e-5f

// k_qwmma smem: union { [As 128x72 | Bs 2x96x72] ; Out 128x200 } halfs
#define QSMEM (128 * OPAD * 2)   // 51200 bytes

// k_fused dynamic smem layout (bytes)
#define F_SH    0                    // float[1920]   h tile
#define F_SH16  7680                 // half[32*72]   fp16 h (padded)
#define F_SAGG  12288                // float[1920]   agg
#define F_SZ    19968                // float[96*32]  z
#define F_EA    32256                // half[96*136]  ea
#define F_W1H   58368                // half[128*40]  W1 fp16
#define F_WRH   68608                // half[64*72]   Wr fp16
#define F_RES   77824                // float[32*64]  R = h @ Wr
#define F_SDEG  86016                // float[30]
#define F_SSE   86136                // int[82]
#define F_SDE   86464                // int[82]
#define F_TOT   86792

// ---------------- scratch (device globals; no allocation allowed) -----------
__device__ float g_h0[NNODES * HID];
__device__ float g_h1[NNODES * HID];
__device__ __half g_Q[(size_t)NNODES * QCOLS];              // ~65 MB fp16
__device__ __half g_hs[(size_t)NNODES * HID];               // fp16 h
__device__ __half g_Ws[(size_t)NLAYERS * QCOLS * HID];      // B  [l][n][64] fp16

// ---------------- prep kernels ----------------------------------------------
// Ws[l][n][k] = fp16(W2p[k][n]); cols 0..2047 from W2, 2048..2111 from b2
__global__ void k_wsplit(const float* __restrict__ W2, const float* __restrict__ b2,
                         __half* __restrict__ Ws, int lo0, int hi0) {
    int idx = lo0 + blockIdx.x * blockDim.x + threadIdx.x;
    if (idx >= hi0) return;
    int k = idx & 63;
    int n = (idx >> 6) % QCOLS;
    int l = idx / (QCOLS * HID);
    float v;
    if (n < 2048) {
        int j = n >> 6, o = n & 63;
        v = W2[(size_t)(l * 32 + j) * 4096 + k * 64 + o];
    } else {
        v = b2[(size_t)l * 4096 + k * 64 + (n - 2048)];
    }
    Ws[idx] = __float2half_rn(v);
}

// h0 = x @ Wp + bp  (+ fp16 copy of h0)
__global__ void k_proj(const float* __restrict__ x, const float* __restrict__ Wp,
                       const float* __restrict__ bp, float* __restrict__ h,
                       __half* __restrict__ hs, int N) {
    int t = blockIdx.x * blockDim.x + threadIdx.x;
    if (t >= N * HID) return;
    int n = t >> 6, c = t & 63;
    const float* xr = x + n * 8;
    float acc = bp[c];
#pragma unroll
    for (int k = 0; k < 8; k++) acc += xr[k] * Wp[k * 64 + c];
    h[t] = acc;
    hs[t] = __float2half_rn(acc);
}

// ---------------- WMMA fp16 GEMM: Q = h(15360x64) @ W^T(64x2112) -------------
// block: 128 M x (2 x 96) N subtiles; fp16 accum; output staged in smem then
// copied to global with coalesced uint4 stores (kills STG-wavefront bloat).
__global__ __launch_bounds__(256, 4) void k_qwmma(const __half* __restrict__ A,
                                                  const __half* __restrict__ B,
                                                  __half* __restrict__ Q) {
    extern __shared__ __half sm[];
    __half* As  = sm;                          // 128 x APAD
    __half* Bs  = sm + 128 * APAD;             // 2 x (96 x BPAD)
    __half* Os  = sm;                          // aliased output stage 128 x OPAD
    const int m0 = blockIdx.y * 128;
    const int n0 = blockIdx.x * 192;
    const int t = threadIdx.x;

    for (int i = t; i < 128 * 8; i += 256) {
        int r = i >> 3, c = (i & 7) * 8;
        *(uint4*)(As + r * APAD + c) = *(const uint4*)(A + (size_t)(m0 + r) * HID + c);
    }
    for (int i = t; i < 2 * 96 * 8; i += 256) {
        int s = i / 768;
        int r = (i % 768) >> 3, c = (i & 7) * 8;
        *(uint4*)(Bs + s * 96 * BPAD + r * BPAD + c) =
            *(const uint4*)(B + (size_t)(n0 + s * 96 + r) * HID + c);
    }
    __syncthreads();

    const int w = t >> 5;
    const int mw = (w & 3) * 32;
    const int nw = (w >> 2) * 48;

    // keep all 12 accumulator tiles live, then stage after operands are dead
    wmma::fragment<wmma::accumulator, 16, 16, 16, __half> acc[2][2][3];
#pragma unroll
    for (int s = 0; s < 2; s++) {
        const __half* Bsub = Bs + s * 96 * BPAD;
#pragma unroll
        for (int i = 0; i < 2; i++)
#pragma unroll
            for (int j = 0; j < 3; j++)
                wmma::fill_fragment(acc[s][i][j], __float2half(0.f));
#pragma unroll
        for (int kk = 0; kk < 4; kk++) {
            wmma::fragment<wmma::matrix_b, 16, 16, 16, __half, wmma::col_major> bf[3];
#pragma unroll
            for (int j = 0; j < 3; j++)
                wmma::load_matrix_sync(bf[j], Bsub + (nw + j * 16) * BPAD + kk * 16, BPAD);
            wmma::fragment<wmma::matrix_a, 16, 16, 16, __half, wmma::row_major> af[2];
#pragma unroll
            for (int i = 0; i < 2; i++)
                wmma::load_matrix_sync(af[i], As + (mw + i * 16) * APAD + kk * 16, APAD);
#pragma unroll
            for (int i = 0; i < 2; i++)
#pragma unroll
                for (int j = 0; j < 3; j++)
                    wmma::mma_sync(acc[s][i][j], af[i], bf[j], acc[s][i][j]);
        }
    }
    __syncthreads();  // operands dead; Os may overwrite As/Bs

    // stage fp16 output tiles to smem (per-warp disjoint regions)
#pragma unroll
    for (int s = 0; s < 2; s++)
#pragma unroll
        for (int i = 0; i < 2; i++)
#pragma unroll
            for (int j = 0; j < 3; j++)
                wmma::store_matrix_sync(
                    Os + (mw + i * 16) * OPAD + s * 96 + nw + j * 16,
                    acc[s][i][j], OPAD, wmma::mem_row_major);
    __syncthreads();

    // coalesced copy smem -> global: 128 rows x 24 uint4
    for (int i = t; i < 128 * 24; i += 256) {
        int r = i / 24, c = (i % 24) * 8;
        *(uint4*)(Q + (size_t)(m0 + r) * QCOLS + n0 + c) = *(const uint4*)(Os + r * OPAD + c);
    }
}

// ---------------- fused per-graph layer kernel --------------------------------
// z + R via WMMA (concurrent warps), msg gather, smem scatter, node update
__global__ __launch_bounds__(FTHREADS, 2) void k_fused(
    const float* __restrict__ h, const int* __restrict__ src, const int* __restrict__ dst,
    const __half* __restrict__ Qh, const float* __restrict__ W1l, const float* __restrict__ b1l,
    const float* __restrict__ Wr, const float* __restrict__ br,
    const float* __restrict__ gamma, const float* __restrict__ beta,
    const float* __restrict__ rmean, const float* __restrict__ rvar,
    float* __restrict__ hout, __half* __restrict__ hs, int E2) {
    extern __shared__ char smraw[];
    float* sh    = (float*)(smraw + F_SH);
    __half* sh16 = (__half*)(smraw + F_SH16);
    float* sagg  = (float*)(smraw + F_SAGG);
    float* sz    = (float*)(smraw + F_SZ);
    __half* ea   = (__half*)(smraw + F_EA);
    __half* w1h  = (__half*)(smraw + F_W1H);
    __half* wrh  = (__half*)(smraw + F_WRH);
    float* Rbuf  = (float*)(smraw + F_RES);
    float* sdeg  = (float*)(smraw + F_SDEG);
    int* sse     = (int*)(smraw + F_SSE);
    int* sde     = (int*)(smraw + F_SDE);

    const int g = blockIdx.x;
    const int tid = threadIdx.x;
    const int w = tid >> 5;
    const int lane = tid & 31;
    const int nbase = g * NPG;

    // phase A: stage h (fp32 + fp16), weights (W1, Wr fp16), zero agg/deg,
    // load edge indices (degree atomics deferred past the sync — no race)
    for (int i = tid; i < NPG * HID; i += FTHREADS) {
        float v = h[nbase * HID + i];
        sh[i] = v;
        sagg[i] = 0.f;
    }
    for (int i = tid; i < 32 * 72; i += FTHREADS) {
        int r = i / 72, c = i - r * 72;
        __half v = __float2half_rn(0.f);
        if (r < NPG && c < 64) v = __float2half_rn(h[nbase * HID + r * 64 + c]);
        sh16[i] = v;
    }
    for (int i = tid; i < 128 * 32; i += FTHREADS)
        w1h[(i >> 5) * 40 + (i & 31)] = __float2half_rn(W1l[i]);
    for (int i = tid; i < 64 * 64; i += FTHREADS)
        wrh[(i >> 6) * 72 + (i & 63)] = __float2half_rn(Wr[i]);
    if (tid < NPG) sdeg[tid] = 0.f;
    if (tid >= 128 && tid < 128 + NEPG) {
        int k = tid - 128;
        int ei = (k < NBR) ? g * NBR + k : E2 + g * NBR + (k - NBR);
        sse[k] = src[ei] - nbase;
        sde[k] = dst[ei] - nbase;
    }
    __syncthreads();

    // phase C: degree atomics (sdeg now safely zeroed) + build ea[96][136]
    if (tid < NEPG) atomicAdd(&sdeg[sde[tid]], 1.0f);
    for (int i = tid; i < 96 * 128; i += FTHREADS) {
        int k = i >> 7, c = i & 127;
        float v = 0.f;
        if (k < NEPG) {
            int node = (c < 64) ? sse[k] : sde[k];
            v = sh[node * 64 + (c & 63)];
        }
        ea[k * 136 + c] = __float2half_rn(v);
    }
    __syncthreads();

    // phase D: warps 0-11: z = ea @ W1 (12 tiles); warps 12-15: R = h @ Wr (8 tiles)
    if (w < 12) {
        int mt = w >> 1, nt = w & 1;
        wmma::fragment<wmma::accumulator, 16, 16, 16, float> acc;
        wmma::fill_fragment(acc, 0.f);
#pragma unroll
        for (int kk = 0; kk < 8; kk++) {
            wmma::fragment<wmma::matrix_a, 16, 16, 16, __half, wmma::row_major> af;
            wmma::fragment<wmma::matrix_b, 16, 16, 16, __half, wmma::row_major> bf;
            wmma::load_matrix_sync(af, ea + (mt * 16) * 136 + kk * 16, 136);
            wmma::load_matrix_sync(bf, w1h + (kk * 16) * 40 + nt * 16, 40);
            wmma::mma_sync(acc, af, bf, acc);
        }
        wmma::store_matrix_sync(sz + mt * 16 * 32 + nt * 16, acc, 32, wmma::mem_row_major);
    } else {
#pragma unroll
        for (int rep = 0; rep < 2; rep++) {
            int T = (w - 12) + rep * 4;      // 0..7
            int mt = T >> 2, nt = T & 3;
            wmma::fragment<wmma::accumulator, 16, 16, 16, float> acc;
            wmma::fill_fragment(acc, 0.f);
#pragma unroll
            for (int kk = 0; kk < 4; kk++) {
                wmma::fragment<wmma::matrix_a, 16, 16, 16, __half, wmma::row_major> af;
                wmma::fragment<wmma::matrix_b, 16, 16, 16, __half, wmma::row_major> bf;
                wmma::load_matrix_sync(af, sh16 + (mt * 16) * 72 + kk * 16, 72);
                wmma::load_matrix_sync(bf, wrh + (kk * 16) * 72 + nt * 16, 72);
                wmma::mma_sync(acc, af, bf, acc);
            }
            wmma::store_matrix_sync(Rbuf + mt * 16 * 64 + nt * 16, acc, 64,
                                    wmma::mem_row_major);
        }
    }
    __syncthreads();

    // phase F: msg gather (warp per edge), bias+relu on z folded in
    const int c = lane & 7;    // o-chunk: outputs c*8 .. c*8+7
    const int jo = lane >> 3;  // j offset within group of 4
    const float b1v = b1l[lane];
    for (int k = w; k < NEPG; k += FTHREADS / 32) {
        int s = sse[k], d = sde[k];
        const __half* Qs = Qh + (size_t)(nbase + s) * QCOLS;
        float zval = fmaxf(sz[k * 32 + lane] + b1v, 0.f);
        float acc[8];
#pragma unroll
        for (int i = 0; i < 8; i++) acc[i] = 0.f;
#pragma unroll
        for (int j0 = 0; j0 < 8; j0++) {
            int j = j0 * 4 + jo;
            float zz = __shfl_sync(0xffffffffu, zval, j);
            uint4 qv = *(const uint4*)(Qs + j * 64 + c * 8);
            const half2* qh = (const half2*)&qv;
#pragma unroll
            for (int i = 0; i < 4; i++) {
                float2 f = __half22float2(qh[i]);
                acc[2 * i] += zz * f.x;
                acc[2 * i + 1] += zz * f.y;
            }
        }
#pragma unroll
        for (int i = 0; i < 8; i++) {
            acc[i] += __shfl_xor_sync(0xffffffffu, acc[i], 8);
            acc[i] += __shfl_xor_sync(0xffffffffu, acc[i], 16);
        }
        int o = c * 8 + jo * 2;
        float2 bias = __half22float2(*(const half2*)(Qs + 2048 + o));
        atomicAdd(&sagg[d * 64 + o], acc[jo * 2] + bias.x);
        atomicAdd(&sagg[d * 64 + o + 1], acc[jo * 2 + 1] + bias.y);
    }
    __syncthreads();

    // phase H: elementwise node update (root GEMM already in Rbuf)
    for (int i = tid; i < NPG * HID; i += FTHREADS) {
        int n = i >> 6, cc = i & 63;
        float h2 = sagg[i] / fmaxf(sdeg[n], 1.0f) + Rbuf[n * 64 + cc] + br[cc];
        float scale = gamma[cc] * rsqrtf(rvar[cc] + BN_EPS);
        h2 = (h2 - rmean[cc]) * scale + beta[cc];
        float r = fmaxf(h2, 0.f) + sh[i];
        hout[nbase * HID + i] = r;
        hs[nbase * HID + i] = __float2half_rn(r);
    }
}

// out[i] = relu([h[u]|h[v]] @ Wm1 + bm1) @ Wm2 + bm2 ; one warp per output row
__global__ void k_final(const float* __restrict__ h, const int* __restrict__ bu,
                        const int* __restrict__ bv, const float* __restrict__ Wm1,
                        const float* __restrict__ bm1, const float* __restrict__ Wm2,
                        const float* __restrict__ bm2, float* __restrict__ out,
                        int nout, int B, int npg) {
    int i = (blockIdx.x * blockDim.x + threadIdx.x) >> 5;
    int lane = threadIdx.x & 31;
    if (i >= nout) return;
    int g = i / B, b = i - g * B;
    int u = bu[b] + g * npg;
    int v = bv[b] + g * npg;
    const float* hu = h + (size_t)u * 64;
    const float* hv = h + (size_t)v * 64;
    float a0 = bm1[lane], a1 = bm1[lane + 32];
#pragma unroll
    for (int k = 0; k < 64; k++) {
        float x0 = hu[k];
        a0 += x0 * Wm1[k * 64 + lane];
        a1 += x0 * Wm1[k * 64 + lane + 32];
    }
#pragma unroll
    for (int k = 0; k < 64; k++) {
        float x1 = hv[k];
        a0 += x1 * Wm1[(64 + k) * 64 + lane];
        a1 += x1 * Wm1[(64 + k) * 64 + lane + 32];
    }
    float r = fmaxf(a0, 0.f) * Wm2[lane] + fmaxf(a1, 0.f) * Wm2[lane + 32];
#pragma unroll
    for (int off = 16; off; off >>= 1) r += __shfl_down_sync(0xffffffffu, r, off);
    if (lane == 0) out[i] = r + bm2[0];
}

extern "C" void kernel_launch(void* const* d_in, const int* in_sizes, int n_in,
                              void* d_out, int out_size) {
    const float* x   = (const float*)d_in[0];
    const int* eidx  = (const int*)d_in[1];
    const int* bu    = (const int*)d_in[2];
    const int* bv    = (const int*)d_in[3];
    int base = (in_sizes[4] == 1) ? 5 : 4;
    const float* Wp    = (const float*)d_in[base + 0];
    const float* bp    = (const float*)d_in[base + 1];
    const float* W1    = (const float*)d_in[base + 2];
    const float* b1    = (const float*)d_in[base + 3];
    const float* W2    = (const float*)d_in[base + 4];
    const float* b2    = (const float*)d_in[base + 5];
    const float* Wr    = (const float*)d_in[base + 6];
    const float* br    = (const float*)d_in[base + 7];
    const float* gamma = (const float*)d_in[base + 8];
    const float* beta  = (const float*)d_in[base + 9];
    const float* rmean = (const float*)d_in[base + 10];
    const float* rvar  = (const float*)d_in[base + 11];
    const float* Wm1   = (const float*)d_in[base + 12];
    const float* bm1   = (const float*)d_in[base + 13];
    const float* Wm2   = (const float*)d_in[base + 14];
    const float* bm2   = (const float*)d_in[base + 15];

    const int Nn = in_sizes[0] / 8;     // 15360
    const int E  = in_sizes[1] / 2;     // 41984
    const int B  = in_sizes[2];         // 41
    const int G  = out_size / B;        // 512
    const int npg = Nn / G;             // 30
    const int* src = eidx;
    const int* dst = eidx + E;
    const int E2 = E / 2;

    static float *p_h0 = nullptr, *p_h1;
    static __half *p_Q, *p_hs, *p_Ws;
    if (!p_h0) {
        cudaGetSymbolAddress((void**)&p_h0, g_h0);
        cudaGetSymbolAddress((void**)&p_h1, g_h1);
        cudaGetSymbolAddress((void**)&p_Q, g_Q);
        cudaGetSymbolAddress((void**)&p_hs, g_hs);
        cudaGetSymbolAddress((void**)&p_Ws, g_Ws);
        cudaFuncSetAttribute(k_qwmma, cudaFuncAttributeMaxDynamicSharedMemorySize, QSMEM);
        cudaFuncSetAttribute(k_fused, cudaFuncAttributeMaxDynamicSharedMemorySize, F_TOT);
    }

    // launches: 0=proj, 1=wsplitA, 2=wsplitB, 3=qwmma(l0), 4=fused(l0),
    // 5=qwmma(l1) <- ncu -s 5 profiles k_qwmma (verify store-path theory)
    const int WTOT = NLAYERS * QCOLS * HID;
    k_proj<<<(Nn * HID + 255) / 256, 256>>>(x, Wp, bp, p_h0, p_hs, Nn);
    k_wsplit<<<(WTOT / 2 + 255) / 256, 256>>>(W2, b2, p_Ws, 0, WTOT / 2);
    k_wsplit<<<(WTOT / 2 + 255) / 256, 256>>>(W2, b2, p_Ws, WTOT / 2, WTOT);

    float* cur = p_h0;
    float* nxt = p_h1;
    dim3 gq(QCOLS / 192, Nn / 128);
    for (int l = 0; l < NLAYERS; l++) {
        k_qwmma<<<gq, 256, QSMEM>>>(p_hs, p_Ws + (size_t)l * QCOLS * HID, p_Q);
        k_fused<<<G, FTHREADS, F_TOT>>>(cur, src, dst, p_Q,
                            W1 + (size_t)l * 128 * 32, b1 + (size_t)l * 32,
                            Wr + (size_t)l * 64 * 64, br + (size_t)l * 64,
                            gamma + (size_t)l * 64, beta + (size_t)l * 64,
                            rmean + (size_t)l * 64, rvar + (size_t)l * 64,
                            nxt, p_hs, E2);
        float* tmp = cur; cur = nxt; nxt = tmp;
    }
    k_final<<<(out_size + 7) / 8, 256>>>(cur, bu, bv, Wm1, bm1, Wm2, bm2,
                                         (float*)d_out, out_size, B, npg);
}